// round 15
// baseline (speedup 1.0000x reference)
#include <cuda_runtime.h>
#include <cuda_fp16.h>

#define B 512
#define N 256
#define E_PER 8192
#define NT (B*N)
#define ET (B*E_PER)
#define FIN 128
#define H 32
#define K 16
#define FOUT 10
#define EPSF 1e-15f
#define FULL 0xffffffffu
#define WSTR 36         // padded pool-weight stride
#define RS   260        // xs transpose stride
#define NTHR 512
#define NW   16
#define NPW  16
#define ZROWS 257       // Z rows incl. zero dummy row 256

// ---------------- globals ----------------
__device__ float g_acc[2] = {0.f, 0.f};
__device__ int   g_ctr = 0;

// ---------------- f32x2 helpers ----------------
__device__ __forceinline__ unsigned long long pk2(float lo, float hi) {
    unsigned long long r;
    asm("mov.b64 %0, {%1,%2};" : "=l"(r)
        : "r"(__float_as_uint(lo)), "r"(__float_as_uint(hi)));
    return r;
}
__device__ __forceinline__ void fma2(unsigned long long& d,
                                     unsigned long long a, unsigned long long b) {
    asm("fma.rn.f32x2 %0, %1, %2, %0;" : "+l"(d) : "l"(a), "l"(b));
}
__device__ __forceinline__ void add2(unsigned long long& d, unsigned long long a) {
    asm("add.rn.f32x2 %0, %0, %1;" : "+l"(d) : "l"(a));
}
__device__ __forceinline__ void upk2(float& lo, float& hi, unsigned long long v) {
    unsigned int a, b2;
    asm("mov.b64 {%0,%1}, %2;" : "=r"(a), "=r"(b2) : "l"(v));
    lo = __uint_as_float(a); hi = __uint_as_float(b2);
}
__device__ __forceinline__ float hsum2(unsigned long long v) {
    float lo, hi; upk2(lo, hi, v); return lo + hi;
}

// ---------------- mega-kernel shared layout ----------------
struct SMem {
    float zs[ZROWS*32];       // Z = h1@Wrel (row 256 = zeros); lin1 ws overlay [0:4096]
    float u[8208];            // h1[8192]; after GEMM2: h1o fp16 [0:4096f) + s [4096:8208)
    float wk[4096];           // 16KB: GEMM2 weights / aggb+hcb strips / reductions / conv2
    float wp[K*WSTR];
    float br[H];
    float bp[K];
    float px[512];
    float adj[256];
    float ssm[256];
    float red[32];
    float tbuf[NW*16];
    float sd[K];
    float sr[H];
    float sh3[H];
    float so[FOUT];
    int wscan[8];
    alignas(16) unsigned short idx[E_PER + 256];  // padded segments; xs overlay fits
    int deg[N];               // TRUE degree
    int start[N];             // padded segment starts (even)
    int cnt[N];
};

// ---------------- mega: entire network, one CTA per graph, 512 threads ------
__global__ __launch_bounds__(NTHR, 2)
void k_mega(const float* __restrict__ x,
            const int* __restrict__ ei,
            const float* __restrict__ Wlin1, const float* __restrict__ blin1,
            const float* __restrict__ Wrel,  const float* __restrict__ brel,
            const float* __restrict__ Wroot, const float* __restrict__ Wpool,
            const float* __restrict__ bpool,
            const float* __restrict__ Wrel2, const float* __restrict__ brel2,
            const float* __restrict__ Wroot2,
            const float* __restrict__ Wlin2, const float* __restrict__ blin2,
            const float* __restrict__ Wlin3, const float* __restrict__ blin3,
            float* __restrict__ out, int out_size)
{
    extern __shared__ char smraw[];
    SMem* sm = (SMem*)smraw;
    int b = blockIdx.x, tid = threadIdx.x;
    int w = tid >> 5, lane = tid & 31;
    int base = b * N;

    // ---- stage pool weights / biases; init cnt ----
    for (int i = tid; i < H*K; i += NTHR) {
        int k = i >> 4, l = i & 15;
        sm->wp[l*WSTR + k] = Wpool[i];
    }
    if (tid < H) sm->br[tid] = brel[tid];
    if (tid < K) sm->bp[tid] = bpool[tid];
    if (tid < N) sm->cnt[tid] = 0;

    // ================= lin1: h1 = x[b] @ W1 + b1 (FFMA2 tile) -> u ==========
    {
        float* ws = sm->zs;                // overlay (Z not yet live)
        float* xs = (float*)sm->idx;       // overlay
        for (int i = tid; i < FIN*H; i += NTHR) ws[i] = Wlin1[i];

        int c0 = (tid & 7) * 4;
        int r0 = (tid >> 3) * 4;
        int lr = tid >> 2;
        int q  = tid & 3;

        float bsv[4];
#pragma unroll
        for (int c = 0; c < 4; c++) bsv[c] = blin1[c0 + c];

        const float* xg = x + (size_t)base * FIN;
        float4 nx[2];
#pragma unroll
        for (int p = 0; p < 2; p++)
            nx[p] = *(const float4*)&xg[(size_t)(lr + p*128)*FIN + q*4];

        unsigned long long acc[2][4];
#pragma unroll
        for (int pr = 0; pr < 2; pr++)
#pragma unroll
            for (int c = 0; c < 4; c++)
                acc[pr][c] = pk2(bsv[c], bsv[c]);

        for (int kt = 0; kt < 8; kt++) {
            __syncthreads();
#pragma unroll
            for (int p = 0; p < 2; p++) {
                int row = lr + p*128;
                xs[(q*4+0)*RS + row] = nx[p].x;
                xs[(q*4+1)*RS + row] = nx[p].y;
                xs[(q*4+2)*RS + row] = nx[p].z;
                xs[(q*4+3)*RS + row] = nx[p].w;
            }
            __syncthreads();
            if (kt < 7) {
#pragma unroll
                for (int p = 0; p < 2; p++)
                    nx[p] = *(const float4*)&xg[(size_t)(lr + p*128)*FIN + (kt+1)*16 + q*4];
            }
#pragma unroll
            for (int k = 0; k < 16; k++) {
                float4 wv = *(const float4*)&ws[(kt*16 + k)*H + c0];
                float4 xa = *(const float4*)&xs[k*RS + r0];
                unsigned long long xp[2], wp2[4];
                xp[0] = pk2(xa.x, xa.y); xp[1] = pk2(xa.z, xa.w);
                wp2[0] = pk2(wv.x, wv.x); wp2[1] = pk2(wv.y, wv.y);
                wp2[2] = pk2(wv.z, wv.z); wp2[3] = pk2(wv.w, wv.w);
#pragma unroll
                for (int pr = 0; pr < 2; pr++) {
                    fma2(acc[pr][0], xp[pr], wp2[0]);
                    fma2(acc[pr][1], xp[pr], wp2[1]);
                    fma2(acc[pr][2], xp[pr], wp2[2]);
                    fma2(acc[pr][3], xp[pr], wp2[3]);
                }
            }
        }
#pragma unroll
        for (int pr = 0; pr < 2; pr++) {
            float lo[4], hi[4];
#pragma unroll
            for (int c = 0; c < 4; c++) upk2(lo[c], hi[c], acc[pr][c]);
            int gr = r0 + 2*pr;
            *(float4*)&sm->u[gr*32 + c0]     = make_float4(lo[0], lo[1], lo[2], lo[3]);
            *(float4*)&sm->u[(gr+1)*32 + c0] = make_float4(hi[0], hi[1], hi[2], hi[3]);
        }
    }
    __syncthreads();

    // ================= GEMM2: Z = h1@Wrel (pass 0), h1o = h1@Wroot fp16 (pass 1)
    {
        for (int i = tid; i < H*H; i += NTHR) {
            sm->wk[i]        = Wrel[i];
            sm->wk[1024 + i] = Wroot[i];
        }
        float* xs = (float*)sm->idx;
        int c0 = (tid & 7) * 4;
        int r0 = (tid >> 3) * 4;
        int lr = tid >> 1, q = tid & 1;

        for (int pass = 0; pass < 2; pass++) {
            const float* wt = sm->wk + pass*1024;
            unsigned long long acc[2][4];
#pragma unroll
            for (int pr = 0; pr < 2; pr++)
#pragma unroll
                for (int c = 0; c < 4; c++) acc[pr][c] = 0ull;

            for (int kt = 0; kt < 2; kt++) {
                __syncthreads();   // prior compute / weight staging done
                {
                    float4 a = *(const float4*)&sm->u[lr*32 + kt*16 + q*8];
                    float4 b2 = *(const float4*)&sm->u[lr*32 + kt*16 + q*8 + 4];
                    xs[(q*8+0)*RS + lr] = a.x;
                    xs[(q*8+1)*RS + lr] = a.y;
                    xs[(q*8+2)*RS + lr] = a.z;
                    xs[(q*8+3)*RS + lr] = a.w;
                    xs[(q*8+4)*RS + lr] = b2.x;
                    xs[(q*8+5)*RS + lr] = b2.y;
                    xs[(q*8+6)*RS + lr] = b2.z;
                    xs[(q*8+7)*RS + lr] = b2.w;
                }
                __syncthreads();
#pragma unroll
                for (int k = 0; k < 16; k++) {
                    float4 wv = *(const float4*)&wt[(kt*16 + k)*H + c0];
                    float4 xa = *(const float4*)&xs[k*RS + r0];
                    unsigned long long xp0 = pk2(xa.x, xa.y), xp1 = pk2(xa.z, xa.w);
                    unsigned long long w0 = pk2(wv.x, wv.x), w1 = pk2(wv.y, wv.y);
                    unsigned long long w2 = pk2(wv.z, wv.z), w3 = pk2(wv.w, wv.w);
                    fma2(acc[0][0], xp0, w0); fma2(acc[0][1], xp0, w1);
                    fma2(acc[0][2], xp0, w2); fma2(acc[0][3], xp0, w3);
                    fma2(acc[1][0], xp1, w0); fma2(acc[1][1], xp1, w1);
                    fma2(acc[1][2], xp1, w2); fma2(acc[1][3], xp1, w3);
                }
            }
            if (pass == 0) {
#pragma unroll
                for (int pr = 0; pr < 2; pr++) {
                    float lo[4], hi[4];
#pragma unroll
                    for (int c = 0; c < 4; c++) upk2(lo[c], hi[c], acc[pr][c]);
                    int gr = r0 + 2*pr;
                    *(float4*)&sm->zs[gr*32 + c0]     = make_float4(lo[0], lo[1], lo[2], lo[3]);
                    *(float4*)&sm->zs[(gr+1)*32 + c0] = make_float4(hi[0], hi[1], hi[2], hi[3]);
                }
            } else {
                __half* ho = (__half*)sm->u;
#pragma unroll
                for (int pr = 0; pr < 2; pr++) {
                    float lo[4], hi[4];
#pragma unroll
                    for (int c = 0; c < 4; c++) upk2(lo[c], hi[c], acc[pr][c]);
                    int gr = r0 + 2*pr;
                    *(__half2*)&ho[gr*32 + c0]       = __floats2half2_rn(lo[0], lo[1]);
                    *(__half2*)&ho[gr*32 + c0 + 2]   = __floats2half2_rn(lo[2], lo[3]);
                    *(__half2*)&ho[(gr+1)*32 + c0]     = __floats2half2_rn(hi[0], hi[1]);
                    *(__half2*)&ho[(gr+1)*32 + c0 + 2] = __floats2half2_rn(hi[2], hi[3]);
                }
            }
        }
    }
    __syncthreads();

    float* sptr = sm->u + 4096;   // s region [257 x 16]

    // ---- sort edges (padded even segments) + zero dummy rows ----
    const int* srcg = ei + b*E_PER;
    const int* dstg = ei + ET + b*E_PER;
    if (tid < 32) sm->zs[256*32 + tid] = 0.f;
    if (tid < 16) sptr[256*16 + tid] = 0.f;
#pragma unroll
    for (int i = 0; i < E_PER/NTHR; i++)
        atomicAdd(&sm->cnt[srcg[tid + i*NTHR] - base], 1);
    __syncthreads();
    {
        int d0 = 0, st0 = 0;
        if (tid < N) {
            d0 = sm->cnt[tid];
            int dp = (d0 + 1) & ~1;
            int v = dp;
#pragma unroll
            for (int off = 1; off < 32; off <<= 1) {
                int nv = __shfl_up_sync(FULL, v, off);
                if (lane >= off) v += nv;
            }
            if (lane == 31) sm->wscan[w] = v;
            st0 = v - dp;
        }
        __syncthreads();
        if (tid < 8) {
            int t = sm->wscan[tid];
#pragma unroll
            for (int off = 1; off < 8; off <<= 1) {
                int nv = __shfl_up_sync(0xff, t, off);
                if (tid >= off) t += nv;
            }
            sm->wscan[tid] = t;
        }
        __syncthreads();
        if (tid < N) {
            if (w > 0) st0 += sm->wscan[w-1];
            sm->deg[tid] = d0;
            sm->start[tid] = st0;
            sm->cnt[tid] = st0;
            if (d0 & 1) sm->idx[st0 + d0] = (unsigned short)256;  // pad -> zero row
        }
    }
    __syncthreads();
#pragma unroll
    for (int i = 0; i < E_PER/NTHR; i++) {
        int u = srcg[tid + i*NTHR] - base;
        int p = atomicAdd(&sm->cnt[u], 1);
        sm->idx[p] = (unsigned short)(dstg[tid + i*NTHR] - base);
    }
    __syncthreads();

    // ---- Phase A: gather Z (packed idx pairs), o = aggZ + h1o + br, pool, px
    unsigned long long px2[8];
#pragma unroll
    for (int k = 0; k < 8; k++) px2[k] = 0ull;

    {
        int grp = lane >> 3, q8 = lane & 7;
        int lk = lane & 15, half_ = lane >> 4;
        float brv = sm->br[lane];
        float bpv = sm->bp[lk];
        const float4* zr = (const float4*)sm->zs;
        const __half* h1o = (const __half*)sm->u;
        float* aggb = sm->wk + w*128;
        float* hcb  = sm->wk + 2048 + w*128;

        for (int u0 = w*NPW; u0 < w*NPW + NPW; u0 += 4) {
#pragma unroll
            for (int g = 0; g < 4; g++) {
                int u = u0 + g;
                int dP = (sm->deg[u] + 1) & ~1;
                int st = sm->start[u];
                ulonglong2 A0 = make_ulonglong2(0ull, 0ull);
                ulonglong2 A1 = make_ulonglong2(0ull, 0ull);
                for (int i = 2*grp; i < dP; i += 8) {
                    unsigned pk = *(const unsigned*)&sm->idx[st + i];
                    int v0 = pk & 0xffff, v1 = pk >> 16;
                    ulonglong2 r0 = *(const ulonglong2*)&zr[v0*8 + q8];
                    ulonglong2 r1 = *(const ulonglong2*)&zr[v1*8 + q8];
                    add2(A0.x, r0.x); add2(A0.y, r0.y);
                    add2(A1.x, r1.x); add2(A1.y, r1.y);
                }
                add2(A0.x, A1.x); add2(A0.y, A1.y);
                unsigned long long t;
                t = __shfl_xor_sync(FULL, A0.x, 8);  add2(A0.x, t);
                t = __shfl_xor_sync(FULL, A0.x, 16); add2(A0.x, t);
                t = __shfl_xor_sync(FULL, A0.y, 8);  add2(A0.y, t);
                t = __shfl_xor_sync(FULL, A0.y, 16); add2(A0.y, t);
                if (lane < 8) *(ulonglong2*)&aggb[g*32 + lane*4] = A0;
            }
            __syncwarp();

            // o = aggZ[lane] + h1o[u][lane] + br[lane]
            float o[4];
#pragma unroll
            for (int g = 0; g < 4; g++) {
                float own = __half2float(h1o[(u0+g)*32 + lane]);
                o[g] = aggb[g*32 + lane] + own + brv;
                hcb[g*32 + lane] = o[g];
            }
            __syncwarp();

            // pool+softmax paired halves
#pragma unroll
            for (int p = 0; p < 2; p++) {
                int g = 2*p + half_;
                unsigned long long sacc = 0ull;
#pragma unroll
                for (int c = 0; c < 8; c++) {
                    ulonglong2 wp2 = *(const ulonglong2*)&sm->wp[lk*WSTR + 4*c];
                    ulonglong2 hq2 = *(const ulonglong2*)&hcb[g*32 + 4*c];
                    fma2(sacc, hq2.x, wp2.x);
                    fma2(sacc, hq2.y, wp2.y);
                }
                float sl = bpv + hsum2(sacc);
                float e = __expf(sl);
                float sum = e;
#pragma unroll
                for (int off = 8; off >= 1; off >>= 1)
                    sum += __shfl_xor_sync(FULL, sum, off, 16);
                sptr[(u0+g)*16 + lk] = e / sum;
            }
            __syncwarp();

            // px rank-1 via packed LDS.128 s-rows
#pragma unroll
            for (int g = 0; g < 4; g++) {
                unsigned long long o2 = pk2(o[g], o[g]);
                const ulonglong2* sr2 = (const ulonglong2*)&sptr[(u0+g)*16];
#pragma unroll
                for (int j = 0; j < 4; j++) {
                    ulonglong2 sv2 = sr2[j];
                    fma2(px2[2*j],   sv2.x, o2);
                    fma2(px2[2*j+1], sv2.y, o2);
                }
            }
        }
    }
    __syncthreads();

    // ---- px reduction across 16 warps (2 rounds of 8 via wk) ----
    float px_reg[16];
#pragma unroll
    for (int kk = 0; kk < 8; kk++) upk2(px_reg[2*kk], px_reg[2*kk+1], px2[kk]);
    for (int round = 0; round < 2; round++) {
        if ((w >> 3) == round) {
#pragma unroll
            for (int k = 0; k < 16; k++)
                sm->wk[(w & 7)*512 + k*32 + lane] = px_reg[k];
        }
        __syncthreads();
        {
            float v = 0.f;
#pragma unroll
            for (int ww = 0; ww < 8; ww++) v += sm->wk[ww*512 + tid];
            if (round == 0) sm->px[tid] = v; else sm->px[tid] += v;
        }
        __syncthreads();
    }

    // ---- Phase B: t = A@s (packed pairs); out_adj = s^T t, ss, den ----
    float oa[8], ob[8];
#pragma unroll
    for (int i = 0; i < 8; i++) { oa[i] = 0.f; ob[i] = 0.f; }
    float den_acc = 0.f;
    {
        int grp8 = lane >> 2, q4 = lane & 3;
        int j = lane & 15, kh = lane >> 4;
        const float4* ssr = (const float4*)sptr;
        for (int u = w*NPW; u < w*NPW + NPW; u++) {
            int d  = sm->deg[u];
            int dP = (d + 1) & ~1;
            int st = sm->start[u];
            ulonglong2 A0 = make_ulonglong2(0ull, 0ull);
            ulonglong2 A1 = make_ulonglong2(0ull, 0ull);
            for (int i = 2*grp8; i < dP; i += 16) {
                unsigned pk = *(const unsigned*)&sm->idx[st + i];
                int v0 = pk & 0xffff, v1 = pk >> 16;
                ulonglong2 r0 = *(const ulonglong2*)&ssr[v0*4 + q4];
                ulonglong2 r1 = *(const ulonglong2*)&ssr[v1*4 + q4];
                add2(A0.x, r0.x); add2(A0.y, r0.y);
                add2(A1.x, r1.x); add2(A1.y, r1.y);
            }
            add2(A0.x, A1.x); add2(A0.y, A1.y);
            unsigned long long t;
            t = __shfl_xor_sync(FULL, A0.x, 4);  add2(A0.x, t);
            t = __shfl_xor_sync(FULL, A0.x, 8);  add2(A0.x, t);
            t = __shfl_xor_sync(FULL, A0.x, 16); add2(A0.x, t);
            t = __shfl_xor_sync(FULL, A0.y, 4);  add2(A0.y, t);
            t = __shfl_xor_sync(FULL, A0.y, 8);  add2(A0.y, t);
            t = __shfl_xor_sync(FULL, A0.y, 16); add2(A0.y, t);
            if (lane < 4) *(ulonglong2*)&sm->tbuf[w*16 + lane*4] = A0;
            __syncwarp();
            float tj = sm->tbuf[w*16 + j];
            float sj = sptr[u*16 + j];
            float4 su0 = *(const float4*)&sptr[u*16 + kh*8];
            float4 su1 = *(const float4*)&sptr[u*16 + kh*8 + 4];
            __syncwarp();

            float v2 = sj*sj;
            v2 += __shfl_xor_sync(FULL, v2, 1, 16);
            v2 += __shfl_xor_sync(FULL, v2, 2, 16);
            v2 += __shfl_xor_sync(FULL, v2, 4, 16);
            v2 += __shfl_xor_sync(FULL, v2, 8, 16);
            den_acc += (float)d * v2;

            oa[0] += su0.x * tj;  ob[0] += su0.x * sj;
            oa[1] += su0.y * tj;  ob[1] += su0.y * sj;
            oa[2] += su0.z * tj;  ob[2] += su0.z * sj;
            oa[3] += su0.w * tj;  ob[3] += su0.w * sj;
            oa[4] += su1.x * tj;  ob[4] += su1.x * sj;
            oa[5] += su1.y * tj;  ob[5] += su1.y * sj;
            oa[6] += su1.z * tj;  ob[6] += su1.z * sj;
            oa[7] += su1.w * tj;  ob[7] += su1.w * sj;
        }
    }
    __syncthreads();

    // ---- reduce out_adj + ss + den (2 rounds of 8 warps) ----
    {
        int j = lane & 15, kh = lane >> 4;
        if (lane == 0) sm->red[w] = den_acc;
        for (int round = 0; round < 2; round++) {
            if ((w >> 3) == round) {
#pragma unroll
                for (int kk = 0; kk < 8; kk++) {
                    sm->wk[(w & 7)*256 + (kh*8+kk)*16 + j] = oa[kk];
                    sm->wk[2048 + (w & 7)*256 + (kh*8+kk)*16 + j] = ob[kk];
                }
            }
            __syncthreads();
            if (tid < 256) {
                float v = 0.f, v2 = 0.f;
#pragma unroll
                for (int ww = 0; ww < 8; ww++) {
                    v  += sm->wk[ww*256 + tid];
                    v2 += sm->wk[2048 + ww*256 + tid];
                }
                if (round == 0) { sm->adj[tid] = v; sm->ssm[tid] = v2; }
                else            { sm->adj[tid] += v; sm->ssm[tid] += v2; }
            }
            __syncthreads();
        }
    }

    // ---- losses ----
    int kq = (tid >> 4) & 15, jq = tid & 15;
    float mincut_part = 0.f;
    if (tid == 0) {
        float den = 0.f;
        for (int i = 0; i < NW; i++) den += sm->red[i];
        float num = 0.f;
        for (int kk = 0; kk < K; kk++) num += sm->adj[kk*K + kk];
        mincut_part = -(num / den);
    }
    float ssv = (tid < 256) ? sm->ssm[tid] : 0.f;
    if (tid < 256) sm->wk[tid] = ssv * ssv;
    __syncthreads();
    for (int off = 128; off > 0; off >>= 1) { if (tid < off) sm->wk[tid] += sm->wk[tid + off]; __syncthreads(); }
    float nrm = sqrtf(sm->wk[0]);
    __syncthreads();
    if (tid < 256) {
        float diff = ssv / nrm - ((kq == jq) ? 0.25f : 0.f);
        sm->wk[tid] = diff * diff;
    }
    __syncthreads();
    for (int off = 128; off > 0; off >>= 1) { if (tid < off) sm->wk[tid] += sm->wk[tid + off]; __syncthreads(); }
    float ortho_part = (tid == 0) ? sqrtf(sm->wk[0]) : 0.f;
    __syncthreads();

    // ---- normalize out_adj ----
    if (tid < 256) {
        float av = (kq == jq) ? 0.f : sm->adj[tid];
        sm->adj[tid] = av;
    }
    __syncthreads();
    if (tid < K) {
        float rs = 0.f;
        for (int jj = 0; jj < K; jj++) rs += sm->adj[tid*K + jj];
        sm->sd[tid] = sqrtf(rs) + EPSF;
    }
    __syncthreads();
    if (tid < 256) sm->adj[tid] = sm->adj[tid] / (sm->sd[kq] * sm->sd[jq]);
    __syncthreads();

    // ---- conv2 ----
    {
        int h = tid & 31, kc = tid >> 5;
        float m1 = 0.f;
#pragma unroll
        for (int jj = 0; jj < K; jj++) m1 += sm->adj[kc*K + jj] * sm->px[jj*H + h];
        sm->wk[kc*H + h] = m1;
    }
    __syncthreads();
    {
        int h = tid & 31, kc = tid >> 5;
        float acc = brel2[h];
        for (int c = 0; c < H; c++)
            acc += sm->wk[kc*H + c] * Wrel2[c*H + h] + sm->px[kc*H + c] * Wroot2[c*H + h];
        sm->wk[512 + kc*H + h] = acc;
    }
    __syncthreads();

    // ---- readout + MLP + log_softmax ----
    if (tid < H) {
        float r = 0.f;
#pragma unroll
        for (int kk = 0; kk < K; kk++) r += sm->wk[512 + kk*H + tid];
        sm->sr[tid] = r;
    }
    __syncthreads();
    if (tid < H) {
        float a2 = blin2[tid];
        for (int c = 0; c < H; c++) a2 += sm->sr[c] * Wlin2[c*H + tid];
        sm->sh3[tid] = fmaxf(a2, 0.f);
    }
    __syncthreads();
    if (tid < FOUT) {
        float a3 = blin3[tid];
        for (int c = 0; c < H; c++) a3 += sm->sh3[c] * Wlin3[c*FOUT + tid];
        sm->so[tid] = a3;
    }
    __syncthreads();
    if (tid == 0) {
        float m = sm->so[0];
        for (int i = 1; i < FOUT; i++) m = fmaxf(m, sm->so[i]);
        float s = 0.f;
        for (int i = 0; i < FOUT; i++) s += __expf(sm->so[i] - m);
        float lse = m + __logf(s);
        for (int i = 0; i < FOUT; i++) out[b*FOUT + i] = sm->so[i] - lse;

        atomicAdd(&g_acc[0], mincut_part * (1.f/(float)B));
        atomicAdd(&g_acc[1], ortho_part  * (1.f/(float)B));
        __threadfence();
        int old = atomicAdd(&g_ctr, 1);
        if (old == B - 1) {
            __threadfence();
            float l0 = g_acc[0], l1 = g_acc[1];
            if (out_size > B*FOUT)     out[B*FOUT]     = l0;
            if (out_size > B*FOUT + 1) out[B*FOUT + 1] = l1;
            g_acc[0] = 0.f; g_acc[1] = 0.f;
            g_ctr = 0;
            __threadfence();
        }
    }
}

// ---------------- launch ----------------
extern "C" void kernel_launch(void* const* d_in, const int* in_sizes, int n_in,
                              void* d_out, int out_size) {
    const float* x     = (const float*)d_in[0];
    const int*   ei    = (const int*)d_in[1];
    const float* Wlin1 = (const float*)d_in[3];
    const float* blin1 = (const float*)d_in[4];
    const float* Wrel1 = (const float*)d_in[5];
    const float* brel1 = (const float*)d_in[6];
    const float* Wroot1= (const float*)d_in[7];
    const float* Wpool = (const float*)d_in[8];
    const float* bpool = (const float*)d_in[9];
    const float* Wrel2 = (const float*)d_in[10];
    const float* brel2 = (const float*)d_in[11];
    const float* Wroot2= (const float*)d_in[12];
    const float* Wlin2 = (const float*)d_in[13];
    const float* blin2 = (const float*)d_in[14];
    const float* Wlin3 = (const float*)d_in[15];
    const float* blin3 = (const float*)d_in[16];
    float* out = (float*)d_out;

    cudaFuncSetAttribute(k_mega, cudaFuncAttributeMaxDynamicSharedMemorySize,
                         (int)sizeof(SMem));

    k_mega<<<B, NTHR, sizeof(SMem)>>>(x, ei, Wlin1, blin1,
                                      Wrel1, brel1, Wroot1, Wpool, bpool,
                                      Wrel2, brel2, Wroot2,
                                      Wlin2, blin2, Wlin3, blin3, out, out_size);
}

// round 16
// speedup vs baseline: 1.0514x; 1.0514x over previous
#include <cuda_runtime.h>
#include <cuda_fp16.h>

#define B 512
#define N 256
#define E_PER 8192
#define NT (B*N)
#define ET (B*E_PER)
#define FIN 128
#define H 32
#define K 16
#define FOUT 10
#define EPSF 1e-15f
#define FULL 0xffffffffu
#define WSTR 36         // padded pool-weight stride
#define RS   260        // xs transpose stride
#define NTHR 512
#define NW   16
#define NPW  16
#define ZROWS 257       // Z rows incl. zero dummy row 256

// ---------------- globals ----------------
__device__ float g_acc[2] = {0.f, 0.f};
__device__ int   g_ctr = 0;

// ---------------- f32x2 helpers ----------------
__device__ __forceinline__ unsigned long long pk2(float lo, float hi) {
    unsigned long long r;
    asm("mov.b64 %0, {%1,%2};" : "=l"(r)
        : "r"(__float_as_uint(lo)), "r"(__float_as_uint(hi)));
    return r;
}
__device__ __forceinline__ void fma2(unsigned long long& d,
                                     unsigned long long a, unsigned long long b) {
    asm("fma.rn.f32x2 %0, %1, %2, %0;" : "+l"(d) : "l"(a), "l"(b));
}
__device__ __forceinline__ void add2(unsigned long long& d, unsigned long long a) {
    asm("add.rn.f32x2 %0, %0, %1;" : "+l"(d) : "l"(a));
}
__device__ __forceinline__ void upk2(float& lo, float& hi, unsigned long long v) {
    unsigned int a, b2;
    asm("mov.b64 {%0,%1}, %2;" : "=r"(a), "=r"(b2) : "l"(v));
    lo = __uint_as_float(a); hi = __uint_as_float(b2);
}
__device__ __forceinline__ float hsum2(unsigned long long v) {
    float lo, hi; upk2(lo, hi, v); return lo + hi;
}

// ---------------- mega-kernel shared layout ----------------
struct SMem {
    float zs[ZROWS*32];       // Z = h1@Wrel (row 256 = zeros); lin1 ws overlay
    float u[8208];            // h1[8192]; after GEMM2: h1o fp16 + s region
    float wk[4096];           // GEMM2 weights / aggb+hcb strips / reductions / conv2
    float wp[K*WSTR];
    float br[H];
    float bp[K];
    float px[512];
    float adj[256];
    float ssm[256];
    float red[32];
    float tbuf[NW*16];
    float sd[K];
    float sr[H];
    float sh3[H];
    float so[FOUT];
    int wscan[8];
    alignas(16) unsigned short idx[E_PER + 256];  // padded segments; xs overlay
    int deg[N];
    int start[N];
    int cnt[N];
};

// ---------------- mega: entire network, one CTA per graph, 512 threads ------
__global__ __launch_bounds__(NTHR, 2)
void k_mega(const float* __restrict__ x,
            const int* __restrict__ ei,
            const float* __restrict__ Wlin1, const float* __restrict__ blin1,
            const float* __restrict__ Wrel,  const float* __restrict__ brel,
            const float* __restrict__ Wroot, const float* __restrict__ Wpool,
            const float* __restrict__ bpool,
            const float* __restrict__ Wrel2, const float* __restrict__ brel2,
            const float* __restrict__ Wroot2,
            const float* __restrict__ Wlin2, const float* __restrict__ blin2,
            const float* __restrict__ Wlin3, const float* __restrict__ blin3,
            float* __restrict__ out, int out_size)
{
    extern __shared__ char smraw[];
    SMem* sm = (SMem*)smraw;
    int b = blockIdx.x, tid = threadIdx.x;
    int w = tid >> 5, lane = tid & 31;
    int base = b * N;

    // ---- stage pool weights / biases; init cnt ----
    for (int i = tid; i < H*K; i += NTHR) {
        int k = i >> 4, l = i & 15;
        sm->wp[l*WSTR + k] = Wpool[i];
    }
    if (tid < H) sm->br[tid] = brel[tid];
    if (tid < K) sm->bp[tid] = bpool[tid];
    if (tid < N) sm->cnt[tid] = 0;

    // ================= lin1: h1 = x[b] @ W1 + b1 (FFMA2 tile) -> u ==========
    {
        float* ws = sm->zs;                // overlay (Z not yet live)
        float* xs = (float*)sm->idx;       // overlay
        for (int i = tid; i < FIN*H; i += NTHR) ws[i] = Wlin1[i];

        int c0 = (tid & 7) * 4;
        int r0 = (tid >> 3) * 4;
        int lr = tid >> 2;
        int q  = tid & 3;

        float bsv[4];
#pragma unroll
        for (int c = 0; c < 4; c++) bsv[c] = blin1[c0 + c];

        const float* xg = x + (size_t)base * FIN;
        float4 nx[2];
#pragma unroll
        for (int p = 0; p < 2; p++)
            nx[p] = *(const float4*)&xg[(size_t)(lr + p*128)*FIN + q*4];

        unsigned long long acc[2][4];
#pragma unroll
        for (int pr = 0; pr < 2; pr++)
#pragma unroll
            for (int c = 0; c < 4; c++)
                acc[pr][c] = pk2(bsv[c], bsv[c]);

        for (int kt = 0; kt < 8; kt++) {
            __syncthreads();
#pragma unroll
            for (int p = 0; p < 2; p++) {
                int row = lr + p*128;
                xs[(q*4+0)*RS + row] = nx[p].x;
                xs[(q*4+1)*RS + row] = nx[p].y;
                xs[(q*4+2)*RS + row] = nx[p].z;
                xs[(q*4+3)*RS + row] = nx[p].w;
            }
            __syncthreads();
            if (kt < 7) {
#pragma unroll
                for (int p = 0; p < 2; p++)
                    nx[p] = *(const float4*)&xg[(size_t)(lr + p*128)*FIN + (kt+1)*16 + q*4];
            }
#pragma unroll
            for (int k = 0; k < 16; k++) {
                float4 wv = *(const float4*)&ws[(kt*16 + k)*H + c0];
                float4 xa = *(const float4*)&xs[k*RS + r0];
                unsigned long long xp[2], wp2[4];
                xp[0] = pk2(xa.x, xa.y); xp[1] = pk2(xa.z, xa.w);
                wp2[0] = pk2(wv.x, wv.x); wp2[1] = pk2(wv.y, wv.y);
                wp2[2] = pk2(wv.z, wv.z); wp2[3] = pk2(wv.w, wv.w);
#pragma unroll
                for (int pr = 0; pr < 2; pr++) {
                    fma2(acc[pr][0], xp[pr], wp2[0]);
                    fma2(acc[pr][1], xp[pr], wp2[1]);
                    fma2(acc[pr][2], xp[pr], wp2[2]);
                    fma2(acc[pr][3], xp[pr], wp2[3]);
                }
            }
        }
#pragma unroll
        for (int pr = 0; pr < 2; pr++) {
            float lo[4], hi[4];
#pragma unroll
            for (int c = 0; c < 4; c++) upk2(lo[c], hi[c], acc[pr][c]);
            int gr = r0 + 2*pr;
            *(float4*)&sm->u[gr*32 + c0]     = make_float4(lo[0], lo[1], lo[2], lo[3]);
            *(float4*)&sm->u[(gr+1)*32 + c0] = make_float4(hi[0], hi[1], hi[2], hi[3]);
        }
    }
    __syncthreads();

    // ================= GEMM2: Z = h1@Wrel (pass 0), h1o = h1@Wroot fp16 (pass 1)
    {
        for (int i = tid; i < H*H; i += NTHR) {
            sm->wk[i]        = Wrel[i];
            sm->wk[1024 + i] = Wroot[i];
        }
        float* xs = (float*)sm->idx;
        int c0 = (tid & 7) * 4;
        int r0 = (tid >> 3) * 4;
        int lr = tid >> 1, q = tid & 1;

        for (int pass = 0; pass < 2; pass++) {
            const float* wt = sm->wk + pass*1024;
            unsigned long long acc[2][4];
#pragma unroll
            for (int pr = 0; pr < 2; pr++)
#pragma unroll
                for (int c = 0; c < 4; c++) acc[pr][c] = 0ull;

            for (int kt = 0; kt < 2; kt++) {
                __syncthreads();
                {
                    float4 a = *(const float4*)&sm->u[lr*32 + kt*16 + q*8];
                    float4 b2 = *(const float4*)&sm->u[lr*32 + kt*16 + q*8 + 4];
                    xs[(q*8+0)*RS + lr] = a.x;
                    xs[(q*8+1)*RS + lr] = a.y;
                    xs[(q*8+2)*RS + lr] = a.z;
                    xs[(q*8+3)*RS + lr] = a.w;
                    xs[(q*8+4)*RS + lr] = b2.x;
                    xs[(q*8+5)*RS + lr] = b2.y;
                    xs[(q*8+6)*RS + lr] = b2.z;
                    xs[(q*8+7)*RS + lr] = b2.w;
                }
                __syncthreads();
#pragma unroll
                for (int k = 0; k < 16; k++) {
                    float4 wv = *(const float4*)&wt[(kt*16 + k)*H + c0];
                    float4 xa = *(const float4*)&xs[k*RS + r0];
                    unsigned long long xp0 = pk2(xa.x, xa.y), xp1 = pk2(xa.z, xa.w);
                    unsigned long long w0 = pk2(wv.x, wv.x), w1 = pk2(wv.y, wv.y);
                    unsigned long long w2 = pk2(wv.z, wv.z), w3 = pk2(wv.w, wv.w);
                    fma2(acc[0][0], xp0, w0); fma2(acc[0][1], xp0, w1);
                    fma2(acc[0][2], xp0, w2); fma2(acc[0][3], xp0, w3);
                    fma2(acc[1][0], xp1, w0); fma2(acc[1][1], xp1, w1);
                    fma2(acc[1][2], xp1, w2); fma2(acc[1][3], xp1, w3);
                }
            }
            if (pass == 0) {
#pragma unroll
                for (int pr = 0; pr < 2; pr++) {
                    float lo[4], hi[4];
#pragma unroll
                    for (int c = 0; c < 4; c++) upk2(lo[c], hi[c], acc[pr][c]);
                    int gr = r0 + 2*pr;
                    *(float4*)&sm->zs[gr*32 + c0]     = make_float4(lo[0], lo[1], lo[2], lo[3]);
                    *(float4*)&sm->zs[(gr+1)*32 + c0] = make_float4(hi[0], hi[1], hi[2], hi[3]);
                }
            } else {
                __half* ho = (__half*)sm->u;
#pragma unroll
                for (int pr = 0; pr < 2; pr++) {
                    float lo[4], hi[4];
#pragma unroll
                    for (int c = 0; c < 4; c++) upk2(lo[c], hi[c], acc[pr][c]);
                    int gr = r0 + 2*pr;
                    *(__half2*)&ho[gr*32 + c0]       = __floats2half2_rn(lo[0], lo[1]);
                    *(__half2*)&ho[gr*32 + c0 + 2]   = __floats2half2_rn(lo[2], lo[3]);
                    *(__half2*)&ho[(gr+1)*32 + c0]     = __floats2half2_rn(hi[0], hi[1]);
                    *(__half2*)&ho[(gr+1)*32 + c0 + 2] = __floats2half2_rn(hi[2], hi[3]);
                }
            }
        }
    }
    __syncthreads();

    float* sptr = sm->u + 4096;   // s region [257 x 16]

    // ---- sort edges (padded even segments) + zero dummy rows ----
    const int* srcg = ei + b*E_PER;
    const int* dstg = ei + ET + b*E_PER;
    if (tid < 32) sm->zs[256*32 + tid] = 0.f;
    if (tid < 16) sptr[256*16 + tid] = 0.f;
#pragma unroll
    for (int i = 0; i < E_PER/NTHR; i++)
        atomicAdd(&sm->cnt[srcg[tid + i*NTHR] - base], 1);
    __syncthreads();
    {
        int d0 = 0, st0 = 0;
        if (tid < N) {
            d0 = sm->cnt[tid];
            int dp = (d0 + 1) & ~1;
            int v = dp;
#pragma unroll
            for (int off = 1; off < 32; off <<= 1) {
                int nv = __shfl_up_sync(FULL, v, off);
                if (lane >= off) v += nv;
            }
            if (lane == 31) sm->wscan[w] = v;
            st0 = v - dp;
        }
        __syncthreads();
        if (tid < 8) {
            int t = sm->wscan[tid];
#pragma unroll
            for (int off = 1; off < 8; off <<= 1) {
                int nv = __shfl_up_sync(0xff, t, off);
                if (tid >= off) t += nv;
            }
            sm->wscan[tid] = t;
        }
        __syncthreads();
        if (tid < N) {
            if (w > 0) st0 += sm->wscan[w-1];
            sm->deg[tid] = d0;
            sm->start[tid] = st0;
            sm->cnt[tid] = st0;
            if (d0 & 1) sm->idx[st0 + d0] = (unsigned short)256;  // pad -> zero row
        }
    }
    __syncthreads();
#pragma unroll
    for (int i = 0; i < E_PER/NTHR; i++) {
        int u = srcg[tid + i*NTHR] - base;
        int p = atomicAdd(&sm->cnt[u], 1);
        sm->idx[p] = (unsigned short)(dstg[tid + i*NTHR] - base);
    }
    __syncthreads();

    // ---- Phase A: gather Z (MLP=4 unrolled), o = aggZ + h1o + br, pool, px
    unsigned long long px2[8];
#pragma unroll
    for (int k = 0; k < 8; k++) px2[k] = 0ull;

    {
        int grp = lane >> 3, q8 = lane & 7;
        int lk = lane & 15, half_ = lane >> 4;
        float brv = sm->br[lane];
        float bpv = sm->bp[lk];
        const float4* zr = (const float4*)sm->zs;
        const __half* h1o = (const __half*)sm->u;
        float* aggb = sm->wk + w*128;
        float* hcb  = sm->wk + 2048 + w*128;

        for (int u0 = w*NPW; u0 < w*NPW + NPW; u0 += 4) {
#pragma unroll
            for (int g = 0; g < 4; g++) {
                int u = u0 + g;
                int dP = (sm->deg[u] + 1) & ~1;
                int st = sm->start[u];
                ulonglong2 A0 = make_ulonglong2(0ull, 0ull);
                ulonglong2 A1 = make_ulonglong2(0ull, 0ull);
                int i = 2*grp;
                // unrolled x2: 2 idx loads + 4 row loads in flight (MLP=4)
                for (; i + 8 < dP; i += 16) {
                    unsigned pa = *(const unsigned*)&sm->idx[st + i];
                    unsigned pb = *(const unsigned*)&sm->idx[st + i + 8];
                    int v0 = pa & 0xffff, v1 = pa >> 16;
                    int v2 = pb & 0xffff, v3 = pb >> 16;
                    ulonglong2 r0 = *(const ulonglong2*)&zr[v0*8 + q8];
                    ulonglong2 r1 = *(const ulonglong2*)&zr[v1*8 + q8];
                    ulonglong2 r2 = *(const ulonglong2*)&zr[v2*8 + q8];
                    ulonglong2 r3 = *(const ulonglong2*)&zr[v3*8 + q8];
                    add2(A0.x, r0.x); add2(A0.y, r0.y);
                    add2(A1.x, r1.x); add2(A1.y, r1.y);
                    add2(A0.x, r2.x); add2(A0.y, r2.y);
                    add2(A1.x, r3.x); add2(A1.y, r3.y);
                }
                if (i < dP) {
                    unsigned pa = *(const unsigned*)&sm->idx[st + i];
                    int v0 = pa & 0xffff, v1 = pa >> 16;
                    ulonglong2 r0 = *(const ulonglong2*)&zr[v0*8 + q8];
                    ulonglong2 r1 = *(const ulonglong2*)&zr[v1*8 + q8];
                    add2(A0.x, r0.x); add2(A0.y, r0.y);
                    add2(A1.x, r1.x); add2(A1.y, r1.y);
                }
                add2(A0.x, A1.x); add2(A0.y, A1.y);
                unsigned long long t;
                t = __shfl_xor_sync(FULL, A0.x, 8);  add2(A0.x, t);
                t = __shfl_xor_sync(FULL, A0.x, 16); add2(A0.x, t);
                t = __shfl_xor_sync(FULL, A0.y, 8);  add2(A0.y, t);
                t = __shfl_xor_sync(FULL, A0.y, 16); add2(A0.y, t);
                if (lane < 8) *(ulonglong2*)&aggb[g*32 + lane*4] = A0;
            }
            __syncwarp();

            // o = aggZ[lane] + h1o[u][lane] + br[lane]
            float o[4];
#pragma unroll
            for (int g = 0; g < 4; g++) {
                float own = __half2float(h1o[(u0+g)*32 + lane]);
                o[g] = aggb[g*32 + lane] + own + brv;
                hcb[g*32 + lane] = o[g];
            }
            __syncwarp();

            // pool+softmax paired halves
#pragma unroll
            for (int p = 0; p < 2; p++) {
                int g = 2*p + half_;
                unsigned long long sacc = 0ull;
#pragma unroll
                for (int c = 0; c < 8; c++) {
                    ulonglong2 wp2 = *(const ulonglong2*)&sm->wp[lk*WSTR + 4*c];
                    ulonglong2 hq2 = *(const ulonglong2*)&hcb[g*32 + 4*c];
                    fma2(sacc, hq2.x, wp2.x);
                    fma2(sacc, hq2.y, wp2.y);
                }
                float sl = bpv + hsum2(sacc);
                float e = __expf(sl);
                float sum = e;
#pragma unroll
                for (int off = 8; off >= 1; off >>= 1)
                    sum += __shfl_xor_sync(FULL, sum, off, 16);
                sptr[(u0+g)*16 + lk] = e / sum;
            }
            __syncwarp();

            // px rank-1 via packed LDS.128 s-rows
#pragma unroll
            for (int g = 0; g < 4; g++) {
                unsigned long long o2 = pk2(o[g], o[g]);
                const ulonglong2* sr2 = (const ulonglong2*)&sptr[(u0+g)*16];
#pragma unroll
                for (int j = 0; j < 4; j++) {
                    ulonglong2 sv2 = sr2[j];
                    fma2(px2[2*j],   sv2.x, o2);
                    fma2(px2[2*j+1], sv2.y, o2);
                }
            }
        }
    }
    __syncthreads();

    // ---- px reduction across 16 warps (2 rounds of 8 via wk) ----
    float px_reg[16];
#pragma unroll
    for (int kk = 0; kk < 8; kk++) upk2(px_reg[2*kk], px_reg[2*kk+1], px2[kk]);
    for (int round = 0; round < 2; round++) {
        if ((w >> 3) == round) {
#pragma unroll
            for (int k = 0; k < 16; k++)
                sm->wk[(w & 7)*512 + k*32 + lane] = px_reg[k];
        }
        __syncthreads();
        {
            float v = 0.f;
#pragma unroll
            for (int ww = 0; ww < 8; ww++) v += sm->wk[ww*512 + tid];
            if (round == 0) sm->px[tid] = v; else sm->px[tid] += v;
        }
        __syncthreads();
    }

    // ---- Phase B: t = A@s (MLP=4 unrolled); out_adj = s^T t, ss, den ----
    float oa[8], ob[8];
#pragma unroll
    for (int i = 0; i < 8; i++) { oa[i] = 0.f; ob[i] = 0.f; }
    float den_acc = 0.f;
    {
        int grp8 = lane >> 2, q4 = lane & 3;
        int j = lane & 15, kh = lane >> 4;
        const float4* ssr = (const float4*)sptr;
        for (int u = w*NPW; u < w*NPW + NPW; u++) {
            int d  = sm->deg[u];
            int dP = (d + 1) & ~1;
            int st = sm->start[u];
            ulonglong2 A0 = make_ulonglong2(0ull, 0ull);
            ulonglong2 A1 = make_ulonglong2(0ull, 0ull);
            int i = 2*grp8;
            for (; i + 16 < dP; i += 32) {
                unsigned pa = *(const unsigned*)&sm->idx[st + i];
                unsigned pb = *(const unsigned*)&sm->idx[st + i + 16];
                int v0 = pa & 0xffff, v1 = pa >> 16;
                int v2 = pb & 0xffff, v3 = pb >> 16;
                ulonglong2 r0 = *(const ulonglong2*)&ssr[v0*4 + q4];
                ulonglong2 r1 = *(const ulonglong2*)&ssr[v1*4 + q4];
                ulonglong2 r2 = *(const ulonglong2*)&ssr[v2*4 + q4];
                ulonglong2 r3 = *(const ulonglong2*)&ssr[v3*4 + q4];
                add2(A0.x, r0.x); add2(A0.y, r0.y);
                add2(A1.x, r1.x); add2(A1.y, r1.y);
                add2(A0.x, r2.x); add2(A0.y, r2.y);
                add2(A1.x, r3.x); add2(A1.y, r3.y);
            }
            if (i < dP) {
                unsigned pa = *(const unsigned*)&sm->idx[st + i];
                int v0 = pa & 0xffff, v1 = pa >> 16;
                ulonglong2 r0 = *(const ulonglong2*)&ssr[v0*4 + q4];
                ulonglong2 r1 = *(const ulonglong2*)&ssr[v1*4 + q4];
                add2(A0.x, r0.x); add2(A0.y, r0.y);
                add2(A1.x, r1.x); add2(A1.y, r1.y);
            }
            add2(A0.x, A1.x); add2(A0.y, A1.y);
            unsigned long long t;
            t = __shfl_xor_sync(FULL, A0.x, 4);  add2(A0.x, t);
            t = __shfl_xor_sync(FULL, A0.x, 8);  add2(A0.x, t);
            t = __shfl_xor_sync(FULL, A0.x, 16); add2(A0.x, t);
            t = __shfl_xor_sync(FULL, A0.y, 4);  add2(A0.y, t);
            t = __shfl_xor_sync(FULL, A0.y, 8);  add2(A0.y, t);
            t = __shfl_xor_sync(FULL, A0.y, 16); add2(A0.y, t);
            if (lane < 4) *(ulonglong2*)&sm->tbuf[w*16 + lane*4] = A0;
            __syncwarp();
            float tj = sm->tbuf[w*16 + j];
            float sj = sptr[u*16 + j];
            float4 su0 = *(const float4*)&sptr[u*16 + kh*8];
            float4 su1 = *(const float4*)&sptr[u*16 + kh*8 + 4];
            __syncwarp();

            float v2 = sj*sj;
            v2 += __shfl_xor_sync(FULL, v2, 1, 16);
            v2 += __shfl_xor_sync(FULL, v2, 2, 16);
            v2 += __shfl_xor_sync(FULL, v2, 4, 16);
            v2 += __shfl_xor_sync(FULL, v2, 8, 16);
            den_acc += (float)d * v2;

            oa[0] += su0.x * tj;  ob[0] += su0.x * sj;
            oa[1] += su0.y * tj;  ob[1] += su0.y * sj;
            oa[2] += su0.z * tj;  ob[2] += su0.z * sj;
            oa[3] += su0.w * tj;  ob[3] += su0.w * sj;
            oa[4] += su1.x * tj;  ob[4] += su1.x * sj;
            oa[5] += su1.y * tj;  ob[5] += su1.y * sj;
            oa[6] += su1.z * tj;  ob[6] += su1.z * sj;
            oa[7] += su1.w * tj;  ob[7] += su1.w * sj;
        }
    }
    __syncthreads();

    // ---- reduce out_adj + ss + den (2 rounds of 8 warps) ----
    {
        int j = lane & 15, kh = lane >> 4;
        if (lane == 0) sm->red[w] = den_acc;
        for (int round = 0; round < 2; round++) {
            if ((w >> 3) == round) {
#pragma unroll
                for (int kk = 0; kk < 8; kk++) {
                    sm->wk[(w & 7)*256 + (kh*8+kk)*16 + j] = oa[kk];
                    sm->wk[2048 + (w & 7)*256 + (kh*8+kk)*16 + j] = ob[kk];
                }
            }
            __syncthreads();
            if (tid < 256) {
                float v = 0.f, v2 = 0.f;
#pragma unroll
                for (int ww = 0; ww < 8; ww++) {
                    v  += sm->wk[ww*256 + tid];
                    v2 += sm->wk[2048 + ww*256 + tid];
                }
                if (round == 0) { sm->adj[tid] = v; sm->ssm[tid] = v2; }
                else            { sm->adj[tid] += v; sm->ssm[tid] += v2; }
            }
            __syncthreads();
        }
    }

    // ---- losses ----
    int kq = (tid >> 4) & 15, jq = tid & 15;
    float mincut_part = 0.f;
    if (tid == 0) {
        float den = 0.f;
        for (int i = 0; i < NW; i++) den += sm->red[i];
        float num = 0.f;
        for (int kk = 0; kk < K; kk++) num += sm->adj[kk*K + kk];
        mincut_part = -(num / den);
    }
    float ssv = (tid < 256) ? sm->ssm[tid] : 0.f;
    if (tid < 256) sm->wk[tid] = ssv * ssv;
    __syncthreads();
    for (int off = 128; off > 0; off >>= 1) { if (tid < off) sm->wk[tid] += sm->wk[tid + off]; __syncthreads(); }
    float nrm = sqrtf(sm->wk[0]);
    __syncthreads();
    if (tid < 256) {
        float diff = ssv / nrm - ((kq == jq) ? 0.25f : 0.f);
        sm->wk[tid] = diff * diff;
    }
    __syncthreads();
    for (int off = 128; off > 0; off >>= 1) { if (tid < off) sm->wk[tid] += sm->wk[tid + off]; __syncthreads(); }
    float ortho_part = (tid == 0) ? sqrtf(sm->wk[0]) : 0.f;
    __syncthreads();

    // ---- normalize out_adj ----
    if (tid < 256) {
        float av = (kq == jq) ? 0.f : sm->adj[tid];
        sm->adj[tid] = av;
    }
    __syncthreads();
    if (tid < K) {
        float rs = 0.f;
        for (int jj = 0; jj < K; jj++) rs += sm->adj[tid*K + jj];
        sm->sd[tid] = sqrtf(rs) + EPSF;
    }
    __syncthreads();
    if (tid < 256) sm->adj[tid] = sm->adj[tid] / (sm->sd[kq] * sm->sd[jq]);
    __syncthreads();

    // ---- conv2 ----
    {
        int h = tid & 31, kc = tid >> 5;
        float m1 = 0.f;
#pragma unroll
        for (int jj = 0; jj < K; jj++) m1 += sm->adj[kc*K + jj] * sm->px[jj*H + h];
        sm->wk[kc*H + h] = m1;
    }
    __syncthreads();
    {
        int h = tid & 31, kc = tid >> 5;
        float acc = brel2[h];
        for (int c = 0; c < H; c++)
            acc += sm->wk[kc*H + c] * Wrel2[c*H + h] + sm->px[kc*H + c] * Wroot2[c*H + h];
        sm->wk[512 + kc*H + h] = acc;
    }
    __syncthreads();

    // ---- readout + MLP + log_softmax ----
    if (tid < H) {
        float r = 0.f;
#pragma unroll
        for (int kk = 0; kk < K; kk++) r += sm->wk[512 + kk*H + tid];
        sm->sr[tid] = r;
    }
    __syncthreads();
    if (tid < H) {
        float a2 = blin2[tid];
        for (int c = 0; c < H; c++) a2 += sm->sr[c] * Wlin2[c*H + tid];
        sm->sh3[tid] = fmaxf(a2, 0.f);
    }
    __syncthreads();
    if (tid < FOUT) {
        float a3 = blin3[tid];
        for (int c = 0; c < H; c++) a3 += sm->sh3[c] * Wlin3[c*FOUT + tid];
        sm->so[tid] = a3;
    }
    __syncthreads();
    if (tid == 0) {
        float m = sm->so[0];
        for (int i = 1; i < FOUT; i++) m = fmaxf(m, sm->so[i]);
        float s = 0.f;
        for (int i = 0; i < FOUT; i++) s += __expf(sm->so[i] - m);
        float lse = m + __logf(s);
        for (int i = 0; i < FOUT; i++) out[b*FOUT + i] = sm->so[i] - lse;

        atomicAdd(&g_acc[0], mincut_part * (1.f/(float)B));
        atomicAdd(&g_acc[1], ortho_part  * (1.f/(float)B));
        __threadfence();
        int old = atomicAdd(&g_ctr, 1);
        if (old == B - 1) {
            __threadfence();
            float l0 = g_acc[0], l1 = g_acc[1];
            if (out_size > B*FOUT)     out[B*FOUT]     = l0;
            if (out_size > B*FOUT + 1) out[B*FOUT + 1] = l1;
            g_acc[0] = 0.f; g_acc[1] = 0.f;
            g_ctr = 0;
            __threadfence();
        }
    }
}

// ---------------- launch ----------------
extern "C" void kernel_launch(void* const* d_in, const int* in_sizes, int n_in,
                              void* d_out, int out_size) {
    const float* x     = (const float*)d_in[0];
    const int*   ei    = (const int*)d_in[1];
    const float* Wlin1 = (const float*)d_in[3];
    const float* blin1 = (const float*)d_in[4];
    const float* Wrel1 = (const float*)d_in[5];
    const float* brel1 = (const float*)d_in[6];
    const float* Wroot1= (const float*)d_in[7];
    const float* Wpool = (const float*)d_in[8];
    const float* bpool = (const float*)d_in[9];
    const float* Wrel2 = (const float*)d_in[10];
    const float* brel2 = (const float*)d_in[11];
    const float* Wroot2= (const float*)d_in[12];
    const float* Wlin2 = (const float*)d_in[13];
    const float* blin2 = (const float*)d_in[14];
    const float* Wlin3 = (const float*)d_in[15];
    const float* blin3 = (const float*)d_in[16];
    float* out = (float*)d_out;

    cudaFuncSetAttribute(k_mega, cudaFuncAttributeMaxDynamicSharedMemorySize,
                         (int)sizeof(SMem));

    k_mega<<<B, NTHR, sizeof(SMem)>>>(x, ei, Wlin1, blin1,
                                      Wrel1, brel1, Wroot1, Wpool, bpool,
                                      Wrel2, brel2, Wroot2,
                                      Wlin2, blin2, Wlin3, blin3, out, out_size);
}